// round 2
// baseline (speedup 1.0000x reference)
#include <cuda_runtime.h>
#include <cuda_bf16.h>
#include <cstdint>

// ---------------- problem constants ----------------
#define BSZ    32
#define HH     56
#define WW_    56
#define CC     384
#define HEADS  12
#define HD     32
#define WIN    7
#define SHIFT  3
#define NTOK   49          // WIN*WIN
#define NWH    8           // H/WIN
#define NWIN   64          // per image
#define TOTW   2048        // BSZ*NWIN
#define MROWS  100352      // TOTW*NTOK = BSZ*H*W
#define MLP    1536

// ---------------- scratch (device globals; no allocs allowed) ----------------
__device__ float g_xw  [MROWS * CC];        // LN1+shift+window-partitioned
__device__ float g_qkv [MROWS * 3 * CC];    // qkv output
__device__ float g_attn[MROWS * CC];        // attention output (window layout)
__device__ float g_y   [MROWS * CC];        // x + proj (spatial layout)
__device__ float g_h2  [MROWS * CC];        // LN2 output
__device__ float g_mlp [MROWS * MLP];       // gelu(fc1) output

// ---------------- helpers ----------------
__device__ __forceinline__ uint32_t tf32cvt(float f) {
    uint32_t u;
    asm("cvt.rna.tf32.f32 %0, %1;" : "=r"(u) : "f"(f));
    return u;
}

// window-layout row -> spatial index (roll-adjusted). Identical map for the
// forward gather (LN1) and the reverse scatter (proj epilogue).
__device__ __forceinline__ int win_row_to_spatial(int r) {
    int w  = r / NTOK, p = r % NTOK;
    int b  = w >> 6, wl = w & 63;
    int wh = wl >> 3, ww = wl & 7;
    int i  = p / WIN, j = p % WIN;
    int hs = wh * WIN + i + SHIFT; if (hs >= HH)  hs -= HH;
    int ws = ww * WIN + j + SHIFT; if (ws >= WW_) ws -= WW_;
    return b * (HH * WW_) + hs * WW_ + ws;
}

// ---------------- LayerNorm (optionally fused with shift+window gather) ------
__global__ __launch_bounds__(128) void ln_kernel(
    const float* __restrict__ in, const float* __restrict__ g,
    const float* __restrict__ be, float* __restrict__ out, int shifted)
{
    int r   = blockIdx.x;
    int src = shifted ? win_row_to_spatial(r) : r;
    const float* row = in + (size_t)src * CC;
    int tid = threadIdx.x;

    float v0 = row[tid], v1 = row[tid + 128], v2 = row[tid + 256];
    float s = v0 + v1 + v2;
    float q = v0 * v0 + v1 * v1 + v2 * v2;
    #pragma unroll
    for (int o = 16; o; o >>= 1) {
        s += __shfl_xor_sync(0xffffffffu, s, o);
        q += __shfl_xor_sync(0xffffffffu, q, o);
    }
    __shared__ float ss[4], sq[4];
    int wid = tid >> 5, lane = tid & 31;
    if (lane == 0) { ss[wid] = s; sq[wid] = q; }
    __syncthreads();
    s = ss[0] + ss[1] + ss[2] + ss[3];
    q = sq[0] + sq[1] + sq[2] + sq[3];
    float m   = s * (1.0f / CC);
    float var = q * (1.0f / CC) - m * m;
    float inv = rsqrtf(var + 1e-5f);

    float* orow = out + (size_t)r * CC;
    orow[tid]       = (v0 - m) * inv * g[tid]       + be[tid];
    orow[tid + 128] = (v1 - m) * inv * g[tid + 128] + be[tid + 128];
    orow[tid + 256] = (v2 - m) * inv * g[tid + 256] + be[tid + 256];
}

// ---------------- attention: one block per (window, head) -------------------
__global__ __launch_bounds__(256) void attn_kernel(
    const float* __restrict__ qkv, const float* __restrict__ rel_bias,
    float* __restrict__ outp)
{
    int bid = blockIdx.x;
    int w   = bid / HEADS;
    int h   = bid % HEADS;

    __shared__ float sq[NTOK][HD + 1];
    __shared__ float sk[NTOK][HD + 1];
    __shared__ float sv[NTOK][HD + 1];
    __shared__ float S [NTOK][NTOK + 1];

    size_t base = (size_t)w * NTOK * (3 * CC) + h * HD;
    for (int t = threadIdx.x; t < NTOK * HD; t += 256) {
        int p = t >> 5, d = t & 31;
        size_t ro = base + (size_t)p * (3 * CC) + d;
        sq[p][d] = qkv[ro];
        sk[p][d] = qkv[ro + CC];
        sv[p][d] = qkv[ro + 2 * CC];
    }
    __syncthreads();

    int wl = w & 63, wh = wl >> 3, ww = wl & 7;

    for (int t = threadIdx.x; t < NTOK * NTOK; t += 256) {
        int i = t / NTOK, j = t % NTOK;
        float acc = 0.f;
        #pragma unroll
        for (int d = 0; d < HD; d++) acc += sq[i][d] * sk[j][d];
        acc *= 0.17677669529663687f;  // 1/sqrt(32)
        int ih = i / WIN, iw = i % WIN, jh = j / WIN, jw = j % WIN;
        acc += __ldg(&rel_bias[((ih - jh + WIN - 1) * (2 * WIN - 1)
                                 + (iw - jw + WIN - 1)) * HEADS + h]);
        // shift mask from index math (region codes on the shifted grid)
        int hi = wh * WIN + ih, wi = ww * WIN + iw;
        int hj = wh * WIN + jh, wj = ww * WIN + jw;
        int ri = (hi < 49 ? 0 : (hi < 53 ? 1 : 2)) * 3 + (wi < 49 ? 0 : (wi < 53 ? 1 : 2));
        int rj = (hj < 49 ? 0 : (hj < 53 ? 1 : 2)) * 3 + (wj < 49 ? 0 : (wj < 53 ? 1 : 2));
        if (ri != rj) acc -= 100.0f;
        S[i][j] = acc;
    }
    __syncthreads();

    // warp-parallel softmax: warp wid handles rows wid, wid+8, ...
    {
        int wid = threadIdx.x >> 5, lane = threadIdx.x & 31;
        for (int i = wid; i < NTOK; i += 8) {
            float v0 = (lane < NTOK) ? S[i][lane] : -1e30f;
            float v1 = (lane + 32 < NTOK) ? S[i][lane + 32] : -1e30f;
            float mx = fmaxf(v0, v1);
            #pragma unroll
            for (int o = 16; o; o >>= 1) mx = fmaxf(mx, __shfl_xor_sync(0xffffffffu, mx, o));
            float e0 = (lane < NTOK) ? __expf(v0 - mx) : 0.f;
            float e1 = (lane + 32 < NTOK) ? __expf(v1 - mx) : 0.f;
            float sum = e0 + e1;
            #pragma unroll
            for (int o = 16; o; o >>= 1) sum += __shfl_xor_sync(0xffffffffu, sum, o);
            float inv = 1.0f / sum;
            if (lane < NTOK)      S[i][lane]      = e0 * inv;
            if (lane + 32 < NTOK) S[i][lane + 32] = e1 * inv;
        }
    }
    __syncthreads();

    for (int t = threadIdx.x; t < NTOK * HD; t += 256) {
        int i = t >> 5, d = t & 31;
        float acc = 0.f;
        #pragma unroll 7
        for (int j = 0; j < NTOK; j++) acc += S[i][j] * sv[j][d];
        outp[(size_t)(w * NTOK + i) * CC + h * HD + d] = acc;
    }
}

// ---------------- tf32 tensor-core GEMM: C = A(MxK) * B(NxK)^T + epilogue ----
// block tile 128x128, BK=16, 8 warps (2x4), warp tile 64x32, mma m16n8k8
__device__ __forceinline__ void stage_store(
    uint32_t (*As)[17], uint32_t (*Bs)[17], int r0, int cb,
    float4 a0, float4 a1, float4 b0, float4 b1)
{
    As[r0][cb]      = tf32cvt(a0.x); As[r0][cb + 1]      = tf32cvt(a0.y);
    As[r0][cb + 2]  = tf32cvt(a0.z); As[r0][cb + 3]      = tf32cvt(a0.w);
    As[r0 + 64][cb]     = tf32cvt(a1.x); As[r0 + 64][cb + 1] = tf32cvt(a1.y);
    As[r0 + 64][cb + 2] = tf32cvt(a1.z); As[r0 + 64][cb + 3] = tf32cvt(a1.w);
    Bs[r0][cb]      = tf32cvt(b0.x); Bs[r0][cb + 1]      = tf32cvt(b0.y);
    Bs[r0][cb + 2]  = tf32cvt(b0.z); Bs[r0][cb + 3]      = tf32cvt(b0.w);
    Bs[r0 + 64][cb]     = tf32cvt(b1.x); Bs[r0 + 64][cb + 1] = tf32cvt(b1.y);
    Bs[r0 + 64][cb + 2] = tf32cvt(b1.z); Bs[r0 + 64][cb + 3] = tf32cvt(b1.w);
}

// stores TWO contiguous columns (col, col+1) as one float2
__device__ __forceinline__ void epi_store2(
    int mode, int row, int col, float v0, float v1, int Nn,
    const float* __restrict__ bias, float* __restrict__ Cout,
    const float* __restrict__ res)
{
    v0 += __ldg(&bias[col]);
    v1 += __ldg(&bias[col + 1]);
    if (mode == 1) {            // exact GELU (fc1)
        v0 = 0.5f * v0 * (1.0f + erff(v0 * 0.70710678118654752f));
        v1 = 0.5f * v1 * (1.0f + erff(v1 * 0.70710678118654752f));
    }
    size_t o;
    if (mode == 2) o = (size_t)win_row_to_spatial(row) * Nn + col;  // window reverse
    else           o = (size_t)row * Nn + col;
    if (mode >= 2) {            // + residual (proj / fc2)
        float2 rr = *(const float2*)(res + o);
        v0 += rr.x; v1 += rr.y;
    }
    float2 st; st.x = v0; st.y = v1;
    *(float2*)(Cout + o) = st;
}

__global__ __launch_bounds__(256) void gemm_tf32(
    const float* __restrict__ A, const float* __restrict__ Bw,
    const float* __restrict__ bias, float* __restrict__ Cout,
    int K, int Nn, int mode, const float* __restrict__ res)
{
    __shared__ uint32_t As[2][128][17];
    __shared__ uint32_t Bs[2][128][17];

    int tid  = threadIdx.x;
    int lane = tid & 31, warp = tid >> 5;
    int wm = warp >> 2, wn = warp & 3;
    int g  = lane >> 2, tg = lane & 3;
    int bm = blockIdx.y * 128, bn = blockIdx.x * 128;

    const float* Ab = A  + (size_t)bm * K;
    const float* Bb = Bw + (size_t)bn * K;
    int r0 = tid >> 2;        // 0..63
    int cb = (tid & 3) * 4;   // 0,4,8,12

    float acc[4][4][4];
    #pragma unroll
    for (int a = 0; a < 4; a++)
        #pragma unroll
        for (int b = 0; b < 4; b++)
            #pragma unroll
            for (int c = 0; c < 4; c++) acc[a][b][c] = 0.f;

    int nk = K / 16;
    float4 a0, a1, b0, b1;

    // prologue: tile 0
    a0 = *(const float4*)(Ab + (size_t)r0 * K + cb);
    a1 = *(const float4*)(Ab + (size_t)(r0 + 64) * K + cb);
    b0 = *(const float4*)(Bb + (size_t)r0 * K + cb);
    b1 = *(const float4*)(Bb + (size_t)(r0 + 64) * K + cb);
    stage_store(As[0], Bs[0], r0, cb, a0, a1, b0, b1);
    __syncthreads();

    int buf = 0;
    for (int kt = 0; kt < nk; kt++) {
        bool more = (kt + 1) < nk;
        if (more) {
            int ko = (kt + 1) * 16 + cb;
            a0 = *(const float4*)(Ab + (size_t)r0 * K + ko);
            a1 = *(const float4*)(Ab + (size_t)(r0 + 64) * K + ko);
            b0 = *(const float4*)(Bb + (size_t)r0 * K + ko);
            b1 = *(const float4*)(Bb + (size_t)(r0 + 64) * K + ko);
        }
        #pragma unroll
        for (int kk = 0; kk < 16; kk += 8) {
            uint32_t af[4][4], bfr[4][2];
            #pragma unroll
            for (int mt = 0; mt < 4; mt++) {
                int rr = wm * 64 + mt * 16 + g;
                af[mt][0] = As[buf][rr][kk + tg];
                af[mt][1] = As[buf][rr + 8][kk + tg];
                af[mt][2] = As[buf][rr][kk + tg + 4];
                af[mt][3] = As[buf][rr + 8][kk + tg + 4];
            }
            #pragma unroll
            for (int nt = 0; nt < 4; nt++) {
                int nn = wn * 32 + nt * 8 + g;
                bfr[nt][0] = Bs[buf][nn][kk + tg];
                bfr[nt][1] = Bs[buf][nn][kk + tg + 4];
            }
            #pragma unroll
            for (int mt = 0; mt < 4; mt++)
                #pragma unroll
                for (int nt = 0; nt < 4; nt++)
                    asm volatile(
                        "mma.sync.aligned.m16n8k8.row.col.f32.tf32.tf32.f32 "
                        "{%0,%1,%2,%3},{%4,%5,%6,%7},{%8,%9},{%0,%1,%2,%3};\n"
                        : "+f"(acc[mt][nt][0]), "+f"(acc[mt][nt][1]),
                          "+f"(acc[mt][nt][2]), "+f"(acc[mt][nt][3])
                        : "r"(af[mt][0]), "r"(af[mt][1]), "r"(af[mt][2]), "r"(af[mt][3]),
                          "r"(bfr[nt][0]), "r"(bfr[nt][1]));
        }
        __syncthreads();
        if (more) {
            stage_store(As[buf ^ 1], Bs[buf ^ 1], r0, cb, a0, a1, b0, b1);
            __syncthreads();
            buf ^= 1;
        }
    }

    #pragma unroll
    for (int mt = 0; mt < 4; mt++) {
        #pragma unroll
        for (int nt = 0; nt < 4; nt++) {
            int row = bm + wm * 64 + mt * 16 + g;
            int col = bn + wn * 32 + nt * 8 + tg * 2;
            epi_store2(mode, row,     col, acc[mt][nt][0], acc[mt][nt][1], Nn, bias, Cout, res);
            epi_store2(mode, row + 8, col, acc[mt][nt][2], acc[mt][nt][3], Nn, bias, Cout, res);
        }
    }
}

// ---------------- launch ----------------
extern "C" void kernel_launch(void* const* d_in, const int* in_sizes, int n_in,
                              void* d_out, int out_size)
{
    const float* x        = (const float*)d_in[0];
    const float* g1       = (const float*)d_in[1];
    const float* b1       = (const float*)d_in[2];
    const float* qkv_w    = (const float*)d_in[3];
    const float* qkv_b    = (const float*)d_in[4];
    const float* rel_bias = (const float*)d_in[5];
    const float* proj_w   = (const float*)d_in[6];
    const float* proj_b   = (const float*)d_in[7];
    const float* g2       = (const float*)d_in[8];
    const float* b2       = (const float*)d_in[9];
    const float* fc1_w    = (const float*)d_in[10];
    const float* fc1_b    = (const float*)d_in[11];
    const float* fc2_w    = (const float*)d_in[12];
    const float* fc2_b    = (const float*)d_in[13];
    float* out = (float*)d_out;

    float *p_xw, *p_qkv, *p_attn, *p_y, *p_h2, *p_mlp;
    cudaGetSymbolAddress((void**)&p_xw,   g_xw);
    cudaGetSymbolAddress((void**)&p_qkv,  g_qkv);
    cudaGetSymbolAddress((void**)&p_attn, g_attn);
    cudaGetSymbolAddress((void**)&p_y,    g_y);
    cudaGetSymbolAddress((void**)&p_h2,   g_h2);
    cudaGetSymbolAddress((void**)&p_mlp,  g_mlp);

    // 1. LN1 + roll(-3,-3) + window partition
    ln_kernel<<<MROWS, 128>>>(x, g1, b1, p_xw, 1);

    // 2. qkv = xw @ qkv_w^T + qkv_b
    gemm_tf32<<<dim3(3 * CC / 128, MROWS / 128), 256>>>(
        p_xw, qkv_w, qkv_b, p_qkv, CC, 3 * CC, 0, nullptr);

    // 3. windowed attention (rel-pos bias + shift mask + softmax + PV)
    attn_kernel<<<TOTW * HEADS, 256>>>(p_qkv, rel_bias, p_attn);

    // 4. y = x + reverse(attn @ proj_w^T + proj_b)
    gemm_tf32<<<dim3(CC / 128, MROWS / 128), 256>>>(
        p_attn, proj_w, proj_b, p_y, CC, CC, 2, x);

    // 5. h2 = LN2(y)
    ln_kernel<<<MROWS, 128>>>(p_y, g2, b2, p_h2, 0);

    // 6. mlp = gelu(h2 @ fc1_w^T + fc1_b)
    gemm_tf32<<<dim3(MLP / 128, MROWS / 128), 256>>>(
        p_h2, fc1_w, fc1_b, p_mlp, CC, MLP, 1, nullptr);

    // 7. out = y + mlp @ fc2_w^T + fc2_b
    gemm_tf32<<<dim3(CC / 128, MROWS / 128), 256>>>(
        p_mlp, fc2_w, fc2_b, out, MLP, CC, 3, p_y);
}

// round 16
// speedup vs baseline: 1.6603x; 1.6603x over previous
#include <cuda_runtime.h>
#include <cuda_bf16.h>
#include <cstdint>

// ---------------- problem constants ----------------
#define BSZ    32
#define HH     56
#define WW_    56
#define CC     384
#define HEADS  12
#define HD     32
#define WIN    7
#define SHIFT  3
#define NTOK   49
#define TOTW   2048
#define MROWS  100352
#define MLP    1536

// weight section offsets in g_wb (bf16)
#define WOFF_QKV  0
#define WOFF_PROJ 442368
#define WOFF_FC1  589824
#define WOFF_FC2  1179648
#define WTOT      1769472

// ---------------- scratch ----------------
__device__ __align__(256) __nv_bfloat16 g_wb  [WTOT];
__device__ __align__(256) __nv_bfloat16 g_xw  [MROWS * CC];
__device__ __align__(256) __nv_bfloat16 g_qkv [MROWS * 3 * CC];
__device__ __align__(256) __nv_bfloat16 g_attn[MROWS * CC];
__device__ __align__(256) float         g_y   [MROWS * CC];
__device__ __align__(256) __nv_bfloat16 g_h2  [MROWS * CC];
__device__ __align__(256) __nv_bfloat16 g_mlp [MROWS * MLP];

// ---------------- small helpers ----------------
__device__ __forceinline__ uint32_t smem_u32(const void* p) {
    uint32_t a;
    asm("{ .reg .u64 t; cvta.to.shared.u64 t, %1; cvt.u32.u64 %0, t; }"
        : "=r"(a) : "l"(p));
    return a;
}
#define LDSM4(r0, r1, r2, r3, a) \
    asm volatile("ldmatrix.sync.aligned.m8n8.x4.shared.b16 {%0,%1,%2,%3}, [%4];" \
                 : "=r"(r0), "=r"(r1), "=r"(r2), "=r"(r3) : "r"(a))
#define CP16(sa_, gp_) \
    asm volatile("cp.async.cg.shared.global [%0], [%1], 16;" \
                 :: "r"((uint32_t)(sa_)), "l"(gp_) : "memory")
#define CPCOMMIT() asm volatile("cp.async.commit_group;" ::: "memory")
#define CPWAIT1()  asm volatile("cp.async.wait_group 1;" ::: "memory")

// window-layout row -> spatial index (roll-adjusted); same map both directions.
__device__ __forceinline__ int win_row_to_spatial(int r) {
    int w  = r / NTOK, p = r % NTOK;
    int b  = w >> 6, wl = w & 63;
    int wh = wl >> 3, ww = wl & 7;
    int i  = p / WIN, j = p % WIN;
    int hs = wh * WIN + i + SHIFT; if (hs >= HH)  hs -= HH;
    int ws = ww * WIN + j + SHIFT; if (ws >= WW_) ws -= WW_;
    return b * (HH * WW_) + hs * WW_ + ws;
}

// ---------------- weight fp32 -> bf16 conversion ----------------
__global__ __launch_bounds__(256) void wconv_kernel(
    const float* __restrict__ w0, const float* __restrict__ w1,
    const float* __restrict__ w2, const float* __restrict__ w3,
    __nv_bfloat16* __restrict__ dst)
{
    int i = blockIdx.x * 256 + threadIdx.x;
    if (i >= WTOT) return;
    float v;
    if      (i < WOFF_PROJ) v = w0[i];
    else if (i < WOFF_FC1)  v = w1[i - WOFF_PROJ];
    else if (i < WOFF_FC2)  v = w2[i - WOFF_FC1];
    else                    v = w3[i - WOFF_FC2];
    dst[i] = __float2bfloat16(v);
}

// ---------------- LayerNorm (optional shift+window gather), bf16 out --------
__global__ __launch_bounds__(128) void ln_kernel(
    const float* __restrict__ in, const float* __restrict__ g,
    const float* __restrict__ be, __nv_bfloat16* __restrict__ out, int shifted)
{
    int r   = blockIdx.x;
    int src = shifted ? win_row_to_spatial(r) : r;
    const float* row = in + (size_t)src * CC;
    int tid = threadIdx.x;

    float v0 = row[tid], v1 = row[tid + 128], v2 = row[tid + 256];
    float s = v0 + v1 + v2;
    float q = v0 * v0 + v1 * v1 + v2 * v2;
    #pragma unroll
    for (int o = 16; o; o >>= 1) {
        s += __shfl_xor_sync(0xffffffffu, s, o);
        q += __shfl_xor_sync(0xffffffffu, q, o);
    }
    __shared__ float ss[4], sq[4];
    int wid = tid >> 5, lane = tid & 31;
    if (lane == 0) { ss[wid] = s; sq[wid] = q; }
    __syncthreads();
    s = ss[0] + ss[1] + ss[2] + ss[3];
    q = sq[0] + sq[1] + sq[2] + sq[3];
    float m   = s * (1.0f / CC);
    float var = q * (1.0f / CC) - m * m;
    float inv = rsqrtf(var + 1e-5f);

    __nv_bfloat16* orow = out + (size_t)r * CC;
    orow[tid]       = __float2bfloat16((v0 - m) * inv * g[tid]       + be[tid]);
    orow[tid + 128] = __float2bfloat16((v1 - m) * inv * g[tid + 128] + be[tid + 128]);
    orow[tid + 256] = __float2bfloat16((v2 - m) * inv * g[tid + 256] + be[tid + 256]);
}

// ---------------- attention: one block per (window, head), bf16 in/out ------
__global__ __launch_bounds__(256) void attn_kernel(
    const __nv_bfloat16* __restrict__ qkv, const float* __restrict__ rel_bias,
    __nv_bfloat16* __restrict__ outp)
{
    int bid = blockIdx.x;
    int w   = bid / HEADS;
    int h   = bid % HEADS;

    __shared__ float sq[NTOK][HD + 1];
    __shared__ float sk[NTOK][HD + 1];
    __shared__ float sv[NTOK][HD + 1];
    __shared__ float S [NTOK][NTOK + 1];

    size_t base = (size_t)w * NTOK * (3 * CC) + h * HD;
    for (int t = threadIdx.x; t < NTOK * HD; t += 256) {
        int p = t >> 5, d = t & 31;
        size_t ro = base + (size_t)p * (3 * CC) + d;
        sq[p][d] = __bfloat162float(qkv[ro]);
        sk[p][d] = __bfloat162float(qkv[ro + CC]);
        sv[p][d] = __bfloat162float(qkv[ro + 2 * CC]);
    }
    __syncthreads();

    int wl = w & 63, wh = wl >> 3, ww = wl & 7;

    for (int t = threadIdx.x; t < NTOK * NTOK; t += 256) {
        int i = t / NTOK, j = t % NTOK;
        float acc = 0.f;
        #pragma unroll
        for (int d = 0; d < HD; d++) acc += sq[i][d] * sk[j][d];
        acc *= 0.17677669529663687f;
        int ih = i / WIN, iw = i % WIN, jh = j / WIN, jw = j % WIN;
        acc += __ldg(&rel_bias[((ih - jh + WIN - 1) * (2 * WIN - 1)
                                 + (iw - jw + WIN - 1)) * HEADS + h]);
        int hi = wh * WIN + ih, wi = ww * WIN + iw;
        int hj = wh * WIN + jh, wj = ww * WIN + jw;
        int ri = (hi < 49 ? 0 : (hi < 53 ? 1 : 2)) * 3 + (wi < 49 ? 0 : (wi < 53 ? 1 : 2));
        int rj = (hj < 49 ? 0 : (hj < 53 ? 1 : 2)) * 3 + (wj < 49 ? 0 : (wj < 53 ? 1 : 2));
        if (ri != rj) acc -= 100.0f;
        S[i][j] = acc;
    }
    __syncthreads();

    {
        int wid = threadIdx.x >> 5, lane = threadIdx.x & 31;
        for (int i = wid; i < NTOK; i += 8) {
            float v0 = (lane < NTOK) ? S[i][lane] : -1e30f;
            float v1 = (lane + 32 < NTOK) ? S[i][lane + 32] : -1e30f;
            float mx = fmaxf(v0, v1);
            #pragma unroll
            for (int o = 16; o; o >>= 1) mx = fmaxf(mx, __shfl_xor_sync(0xffffffffu, mx, o));
            float e0 = (lane < NTOK) ? __expf(v0 - mx) : 0.f;
            float e1 = (lane + 32 < NTOK) ? __expf(v1 - mx) : 0.f;
            float sum = e0 + e1;
            #pragma unroll
            for (int o = 16; o; o >>= 1) sum += __shfl_xor_sync(0xffffffffu, sum, o);
            float inv = 1.0f / sum;
            if (lane < NTOK)      S[i][lane]      = e0 * inv;
            if (lane + 32 < NTOK) S[i][lane + 32] = e1 * inv;
        }
    }
    __syncthreads();

    for (int t = threadIdx.x; t < NTOK * HD; t += 256) {
        int i = t >> 5, d = t & 31;
        float acc = 0.f;
        #pragma unroll 7
        for (int j = 0; j < NTOK; j++) acc += S[i][j] * sv[j][d];
        outp[(size_t)(w * NTOK + i) * CC + h * HD + d] = __float2bfloat16(acc);
    }
}

// ---------------- bf16 tensor GEMM: C = A(MxK) * B(NxK)^T + epilogue --------
// block 128x128, 4 warps (2x2), warp tile 64x64, mma m16n8k16, BK=32,
// 2-stage cp.async pipeline, ldmatrix.x4 fragment loads.
// smem row stride 80B (conflict-free for both STS and LDSM phases).
#define STG 20480   // one stage: A(128x80B) + B(128x80B)

__device__ __forceinline__ void epi2(
    int mode, size_t o, int col, float v0, float v1,
    const float* __restrict__ bias, void* __restrict__ C,
    const float* __restrict__ res)
{
    float2 bb = *(const float2*)(bias + col);
    v0 += bb.x; v1 += bb.y;
    if (mode == 1) {
        v0 = 0.5f * v0 * (1.0f + erff(v0 * 0.70710678118654752f));
        v1 = 0.5f * v1 * (1.0f + erff(v1 * 0.70710678118654752f));
    }
    if (mode >= 2) {
        float2 rr = *(const float2*)(res + o);
        float2 st; st.x = v0 + rr.x; st.y = v1 + rr.y;
        *(float2*)((float*)C + o) = st;
    } else {
        __nv_bfloat162 hh;
        hh.x = __float2bfloat16(v0); hh.y = __float2bfloat16(v1);
        *(__nv_bfloat162*)((__nv_bfloat16*)C + o) = hh;
    }
}

__global__ __launch_bounds__(128) void gemm_bf16(
    const __nv_bfloat16* __restrict__ A, const __nv_bfloat16* __restrict__ Bw,
    const float* __restrict__ bias, void* __restrict__ Cout,
    int K, int Nn, int mode, const float* __restrict__ res)
{
    __shared__ __align__(16) char smem[2 * STG];
    uint32_t sb = smem_u32(smem);
    int tid = threadIdx.x, lane = tid & 31, warp = tid >> 5;
    int wm = warp >> 1, wn = warp & 1;
    int g  = lane >> 2, tg = lane & 3;
    int bm = blockIdx.y * 128, bn = blockIdx.x * 128;

    const __nv_bfloat16* Ag = A  + (size_t)(bm + tid) * K;   // thread's A row
    const __nv_bfloat16* Bg = Bw + (size_t)(bn + tid) * K;   // thread's B row
    uint32_t sa = sb + tid * 80;

    // ldmatrix lane-address offsets (within a stage, before +kk*32)
    int grp = lane >> 3, wr = lane & 7;
    uint32_t aoff[4], boff[4];
    #pragma unroll
    for (int mt = 0; mt < 4; mt++)
        aoff[mt] = (uint32_t)(wm * 64 + mt * 16 + (grp & 1) * 8 + wr) * 80
                 + (uint32_t)(grp >> 1) * 16;
    #pragma unroll
    for (int np = 0; np < 4; np++)   // n-pair: covers nt=2*np, 2*np+1
        boff[np] = 10240
                 + (uint32_t)(wn * 64 + np * 16 + (grp >> 1) * 8 + wr) * 80
                 + (uint32_t)(grp & 1) * 16;

    float acc[4][8][4];
    #pragma unroll
    for (int a = 0; a < 4; a++)
        #pragma unroll
        for (int b = 0; b < 8; b++)
            #pragma unroll
            for (int c = 0; c < 4; c++) acc[a][b][c] = 0.f;

    int nk = K >> 5;

    // prologue: stage 0 <- kt 0
    #pragma unroll
    for (int c = 0; c < 4; c++) {
        CP16(sa + c * 16,         Ag + c * 8);
        CP16(sa + 10240 + c * 16, Bg + c * 8);
    }
    CPCOMMIT();

    for (int kt = 0; kt < nk; kt++) {
        int s = kt & 1;
        if (kt + 1 < nk) {
            const __nv_bfloat16* ag = Ag + (kt + 1) * 32;
            const __nv_bfloat16* bg = Bg + (kt + 1) * 32;
            uint32_t d = sa + (s ^ 1) * STG;
            #pragma unroll
            for (int c = 0; c < 4; c++) {
                CP16(d + c * 16,         ag + c * 8);
                CP16(d + 10240 + c * 16, bg + c * 8);
            }
        }
        CPCOMMIT();
        CPWAIT1();
        __syncthreads();

        uint32_t stgB = sb + s * STG;
        #pragma unroll
        for (int kk = 0; kk < 2; kk++) {       // two k16 halves of BK=32
            uint32_t kbyte = kk * 32;
            uint32_t af[4][4], bf_[8][2];
            #pragma unroll
            for (int mt = 0; mt < 4; mt++)
                LDSM4(af[mt][0], af[mt][1], af[mt][2], af[mt][3],
                      stgB + aoff[mt] + kbyte);
            #pragma unroll
            for (int np = 0; np < 4; np++)
                LDSM4(bf_[2 * np][0], bf_[2 * np][1],
                      bf_[2 * np + 1][0], bf_[2 * np + 1][1],
                      stgB + boff[np] + kbyte);
            #pragma unroll
            for (int mt = 0; mt < 4; mt++)
                #pragma unroll
                for (int nt = 0; nt < 8; nt++)
                    asm volatile(
                        "mma.sync.aligned.m16n8k16.row.col.f32.bf16.bf16.f32 "
                        "{%0,%1,%2,%3},{%4,%5,%6,%7},{%8,%9},{%0,%1,%2,%3};\n"
                        : "+f"(acc[mt][nt][0]), "+f"(acc[mt][nt][1]),
                          "+f"(acc[mt][nt][2]), "+f"(acc[mt][nt][3])
                        : "r"(af[mt][0]), "r"(af[mt][1]), "r"(af[mt][2]), "r"(af[mt][3]),
                          "r"(bf_[nt][0]), "r"(bf_[nt][1]));
        }
        __syncthreads();
    }

    // epilogue
    #pragma unroll
    for (int mt = 0; mt < 4; mt++) {
        int r0 = bm + wm * 64 + mt * 16 + g;
        int r1 = r0 + 8;
        size_t ob0 = (size_t)((mode == 2) ? win_row_to_spatial(r0) : r0) * Nn;
        size_t ob1 = (size_t)((mode == 2) ? win_row_to_spatial(r1) : r1) * Nn;
        #pragma unroll
        for (int nt = 0; nt < 8; nt++) {
            int col = bn + wn * 64 + nt * 8 + tg * 2;
            epi2(mode, ob0 + col, col, acc[mt][nt][0], acc[mt][nt][1], bias, Cout, res);
            epi2(mode, ob1 + col, col, acc[mt][nt][2], acc[mt][nt][3], bias, Cout, res);
        }
    }
}

// ---------------- launch ----------------
extern "C" void kernel_launch(void* const* d_in, const int* in_sizes, int n_in,
                              void* d_out, int out_size)
{
    const float* x        = (const float*)d_in[0];
    const float* g1       = (const float*)d_in[1];
    const float* b1       = (const float*)d_in[2];
    const float* qkv_w    = (const float*)d_in[3];
    const float* qkv_b    = (const float*)d_in[4];
    const float* rel_bias = (const float*)d_in[5];
    const float* proj_w   = (const float*)d_in[6];
    const float* proj_b   = (const float*)d_in[7];
    const float* g2       = (const float*)d_in[8];
    const float* b2       = (const float*)d_in[9];
    const float* fc1_w    = (const float*)d_in[10];
    const float* fc1_b    = (const float*)d_in[11];
    const float* fc2_w    = (const float*)d_in[12];
    const float* fc2_b    = (const float*)d_in[13];
    float* out = (float*)d_out;

    __nv_bfloat16 *p_wb, *p_xw, *p_qkv, *p_attn, *p_h2, *p_mlp;
    float *p_y;
    cudaGetSymbolAddress((void**)&p_wb,   g_wb);
    cudaGetSymbolAddress((void**)&p_xw,   g_xw);
    cudaGetSymbolAddress((void**)&p_qkv,  g_qkv);
    cudaGetSymbolAddress((void**)&p_attn, g_attn);
    cudaGetSymbolAddress((void**)&p_y,    g_y);
    cudaGetSymbolAddress((void**)&p_h2,   g_h2);
    cudaGetSymbolAddress((void**)&p_mlp,  g_mlp);

    // 0. weights -> bf16
    wconv_kernel<<<(WTOT + 255) / 256, 256>>>(qkv_w, proj_w, fc1_w, fc2_w, p_wb);

    // 1. LN1 + roll(-3,-3) + window partition (bf16 out)
    ln_kernel<<<MROWS, 128>>>(x, g1, b1, p_xw, 1);

    // 2. qkv = xw @ qkv_w^T + qkv_b  (bf16 out)
    gemm_bf16<<<dim3(3 * CC / 128, MROWS / 128), 128>>>(
        p_xw, p_wb + WOFF_QKV, qkv_b, p_qkv, CC, 3 * CC, 0, nullptr);

    // 3. windowed attention (bf16 out)
    attn_kernel<<<TOTW * HEADS, 256>>>(p_qkv, rel_bias, p_attn);

    // 4. y = x + reverse(attn @ proj_w^T + proj_b)   (fp32 out)
    gemm_bf16<<<dim3(CC / 128, MROWS / 128), 128>>>(
        p_attn, p_wb + WOFF_PROJ, proj_b, p_y, CC, CC, 2, x);

    // 5. h2 = LN2(y)  (bf16 out)
    ln_kernel<<<MROWS, 128>>>(p_y, g2, b2, p_h2, 0);

    // 6. mlp = gelu(h2 @ fc1_w^T + fc1_b)  (bf16 out)
    gemm_bf16<<<dim3(MLP / 128, MROWS / 128), 128>>>(
        p_h2, p_wb + WOFF_FC1, fc1_b, p_mlp, CC, MLP, 1, nullptr);

    // 7. out = y + mlp @ fc2_w^T + fc2_b  (fp32 out)
    gemm_bf16<<<dim3(CC / 128, MROWS / 128), 128>>>(
        p_mlp, p_wb + WOFF_FC2, fc2_b, out, MLP, CC, 3, p_y);
}